// round 1
// baseline (speedup 1.0000x reference)
#include <cuda_runtime.h>
#include <cuda_bf16.h>

// Problem constants
static constexpr int HID  = 1024;     // hidden
static constexpr int NB   = 4;        // batch
static constexpr int SEQ  = 2048;     // seq len
static constexpr int ROWS = NB * SEQ; // 8192

// Scratch (device globals: allocation-free rule)
__device__ float g_Q[(size_t)ROWS * HID];
__device__ float g_K[(size_t)ROWS * HID];
__device__ float g_V[(size_t)ROWS * HID];
__device__ float g_Sc[(size_t)NB * SEQ * SEQ];

// ---------------------------------------------------------------------------
// GEMM NT: C[m,n] = alpha * sum_k A[m,k] * B[n,k] (+ bias[n])
// A: [M,K] row-major, B: [N,K] row-major. 128x128x8 tile, 256 thr, 8x8/thread.
// blockIdx.z batches via sA/sB/sC element strides.
// ---------------------------------------------------------------------------
__global__ void __launch_bounds__(256)
gemm_nt_kernel(const float* __restrict__ A, const float* __restrict__ Bm,
               const float* __restrict__ bias, float* __restrict__ C,
               int M, int N, int K, float alpha,
               size_t sA, size_t sB, size_t sC)
{
    __shared__ float As[8][128];
    __shared__ float Bs[8][128];

    const int tid  = threadIdx.x;
    const int lrow = tid >> 1;          // 0..127
    const int lcol = (tid & 1) << 2;    // 0 or 4
    const int ty   = tid >> 4;          // 0..15
    const int tx   = tid & 15;          // 0..15

    A  += blockIdx.z * sA + (size_t)blockIdx.y * 128 * K;
    Bm += blockIdx.z * sB + (size_t)blockIdx.x * 128 * K;
    C  += blockIdx.z * sC;

    float acc[8][8];
#pragma unroll
    for (int i = 0; i < 8; i++)
#pragma unroll
        for (int j = 0; j < 8; j++) acc[i][j] = 0.0f;

    for (int k0 = 0; k0 < K; k0 += 8) {
        float4 av = *(const float4*)(A  + (size_t)lrow * K + k0 + lcol);
        float4 bv = *(const float4*)(Bm + (size_t)lrow * K + k0 + lcol);
        As[lcol + 0][lrow] = av.x; As[lcol + 1][lrow] = av.y;
        As[lcol + 2][lrow] = av.z; As[lcol + 3][lrow] = av.w;
        Bs[lcol + 0][lrow] = bv.x; Bs[lcol + 1][lrow] = bv.y;
        Bs[lcol + 2][lrow] = bv.z; Bs[lcol + 3][lrow] = bv.w;
        __syncthreads();
#pragma unroll
        for (int kk = 0; kk < 8; kk++) {
            float4 a0 = *(const float4*)&As[kk][ty * 4];
            float4 a1 = *(const float4*)&As[kk][64 + ty * 4];
            float4 b0 = *(const float4*)&Bs[kk][tx * 4];
            float4 b1 = *(const float4*)&Bs[kk][64 + tx * 4];
            float a[8] = {a0.x, a0.y, a0.z, a0.w, a1.x, a1.y, a1.z, a1.w};
            float b[8] = {b0.x, b0.y, b0.z, b0.w, b1.x, b1.y, b1.z, b1.w};
#pragma unroll
            for (int i = 0; i < 8; i++)
#pragma unroll
                for (int j = 0; j < 8; j++)
                    acc[i][j] = fmaf(a[i], b[j], acc[i][j]);
        }
        __syncthreads();
    }

    const int ncol0 = blockIdx.x * 128 + tx * 4;
    float4 bia0 = make_float4(0.f, 0.f, 0.f, 0.f), bia1 = bia0;
    if (bias) {
        bia0 = *(const float4*)(bias + ncol0);
        bia1 = *(const float4*)(bias + ncol0 + 64);
    }
#pragma unroll
    for (int i = 0; i < 8; i++) {
        int row = blockIdx.y * 128 + ((i < 4) ? (ty * 4 + i) : (64 + ty * 4 + i - 4));
        float* cptr = C + (size_t)row * N + ncol0;
        float4 o0, o1;
        o0.x = fmaf(alpha, acc[i][0], bia0.x);
        o0.y = fmaf(alpha, acc[i][1], bia0.y);
        o0.z = fmaf(alpha, acc[i][2], bia0.z);
        o0.w = fmaf(alpha, acc[i][3], bia0.w);
        o1.x = fmaf(alpha, acc[i][4], bia1.x);
        o1.y = fmaf(alpha, acc[i][5], bia1.y);
        o1.z = fmaf(alpha, acc[i][6], bia1.z);
        o1.w = fmaf(alpha, acc[i][7], bia1.w);
        *(float4*)cptr        = o0;
        *(float4*)(cptr + 64) = o1;
    }
}

// ---------------------------------------------------------------------------
// GEMM NN: C[m,n] = sum_k A[m,k] * B[k,n]
// A: [M,K] row-major (P), B: [K,N] row-major (V).
// ---------------------------------------------------------------------------
__global__ void __launch_bounds__(256)
gemm_nn_kernel(const float* __restrict__ A, const float* __restrict__ Bm,
               float* __restrict__ C,
               int M, int N, int K,
               size_t sA, size_t sB, size_t sC)
{
    __shared__ float As[8][128];
    __shared__ float Bs[8][128];

    const int tid  = threadIdx.x;
    const int lrow = tid >> 1;          // A-load row
    const int lcol = (tid & 1) << 2;
    const int krow = tid >> 5;          // B-load k row 0..7
    const int bcol = (tid & 31) << 2;   // B-load col 0..124
    const int ty   = tid >> 4;
    const int tx   = tid & 15;

    A  += blockIdx.z * sA + (size_t)blockIdx.y * 128 * K;
    Bm += blockIdx.z * sB + (size_t)blockIdx.x * 128;
    C  += blockIdx.z * sC;

    float acc[8][8];
#pragma unroll
    for (int i = 0; i < 8; i++)
#pragma unroll
        for (int j = 0; j < 8; j++) acc[i][j] = 0.0f;

    for (int k0 = 0; k0 < K; k0 += 8) {
        float4 av = *(const float4*)(A + (size_t)lrow * K + k0 + lcol);
        As[lcol + 0][lrow] = av.x; As[lcol + 1][lrow] = av.y;
        As[lcol + 2][lrow] = av.z; As[lcol + 3][lrow] = av.w;
        float4 bv = *(const float4*)(Bm + (size_t)(k0 + krow) * N + bcol);
        *(float4*)&Bs[krow][bcol] = bv;
        __syncthreads();
#pragma unroll
        for (int kk = 0; kk < 8; kk++) {
            float4 a0 = *(const float4*)&As[kk][ty * 4];
            float4 a1 = *(const float4*)&As[kk][64 + ty * 4];
            float4 b0 = *(const float4*)&Bs[kk][tx * 4];
            float4 b1 = *(const float4*)&Bs[kk][64 + tx * 4];
            float a[8] = {a0.x, a0.y, a0.z, a0.w, a1.x, a1.y, a1.z, a1.w};
            float b[8] = {b0.x, b0.y, b0.z, b0.w, b1.x, b1.y, b1.z, b1.w};
#pragma unroll
            for (int i = 0; i < 8; i++)
#pragma unroll
                for (int j = 0; j < 8; j++)
                    acc[i][j] = fmaf(a[i], b[j], acc[i][j]);
        }
        __syncthreads();
    }

    const int ncol0 = blockIdx.x * 128 + tx * 4;
#pragma unroll
    for (int i = 0; i < 8; i++) {
        int row = blockIdx.y * 128 + ((i < 4) ? (ty * 4 + i) : (64 + ty * 4 + i - 4));
        float* cptr = C + (size_t)row * N + ncol0;
        float4 o0 = make_float4(acc[i][0], acc[i][1], acc[i][2], acc[i][3]);
        float4 o1 = make_float4(acc[i][4], acc[i][5], acc[i][6], acc[i][7]);
        *(float4*)cptr        = o0;
        *(float4*)(cptr + 64) = o1;
    }
}

// ---------------------------------------------------------------------------
// Row softmax over 2048 elements. One block (256 thr) per row; 8 elems/thread.
// ---------------------------------------------------------------------------
__global__ void __launch_bounds__(256)
softmax_kernel(float* __restrict__ Sc)
{
    __shared__ float red[256];
    float* row = Sc + (size_t)blockIdx.x * SEQ;
    const int tid = threadIdx.x;

    float4 v0 = ((const float4*)row)[tid];
    float4 v1 = ((const float4*)row)[tid + 256];

    float m = fmaxf(fmaxf(fmaxf(v0.x, v0.y), fmaxf(v0.z, v0.w)),
                    fmaxf(fmaxf(v1.x, v1.y), fmaxf(v1.z, v1.w)));
    red[tid] = m;
    __syncthreads();
#pragma unroll
    for (int s = 128; s > 0; s >>= 1) {
        if (tid < s) red[tid] = fmaxf(red[tid], red[tid + s]);
        __syncthreads();
    }
    m = red[0];
    __syncthreads();

    v0.x = __expf(v0.x - m); v0.y = __expf(v0.y - m);
    v0.z = __expf(v0.z - m); v0.w = __expf(v0.w - m);
    v1.x = __expf(v1.x - m); v1.y = __expf(v1.y - m);
    v1.z = __expf(v1.z - m); v1.w = __expf(v1.w - m);

    float sum = v0.x + v0.y + v0.z + v0.w + v1.x + v1.y + v1.z + v1.w;
    red[tid] = sum;
    __syncthreads();
#pragma unroll
    for (int s = 128; s > 0; s >>= 1) {
        if (tid < s) red[tid] += red[tid + s];
        __syncthreads();
    }
    float inv = 1.0f / red[0];

    v0.x *= inv; v0.y *= inv; v0.z *= inv; v0.w *= inv;
    v1.x *= inv; v1.y *= inv; v1.z *= inv; v1.w *= inv;
    ((float4*)row)[tid]       = v0;
    ((float4*)row)[tid + 256] = v1;
}

// ---------------------------------------------------------------------------
// Launch
// ---------------------------------------------------------------------------
extern "C" void kernel_launch(void* const* d_in, const int* in_sizes, int n_in,
                              void* d_out, int out_size)
{
    const float* X  = (const float*)d_in[0];
    const float* Wq = (const float*)d_in[1];
    const float* bq = (const float*)d_in[2];
    const float* Wk = (const float*)d_in[3];
    const float* bk = (const float*)d_in[4];
    const float* Wv = (const float*)d_in[5];
    const float* bv = (const float*)d_in[6];
    float* out = (float*)d_out;

    float *Q, *K, *V, *Sc;
    cudaGetSymbolAddress((void**)&Q,  g_Q);
    cudaGetSymbolAddress((void**)&K,  g_K);
    cudaGetSymbolAddress((void**)&V,  g_V);
    cudaGetSymbolAddress((void**)&Sc, g_Sc);

    dim3 blk(256);

    // QKV projections: [8192,1024] = X[8192,1024] @ W[1024,1024]^T + b
    dim3 gq(HID / 128, ROWS / 128, 1);
    gemm_nt_kernel<<<gq, blk>>>(X, Wq, bq, Q, ROWS, HID, HID, 1.0f, 0, 0, 0);
    gemm_nt_kernel<<<gq, blk>>>(X, Wk, bk, K, ROWS, HID, HID, 1.0f, 0, 0, 0);
    gemm_nt_kernel<<<gq, blk>>>(X, Wv, bv, V, ROWS, HID, HID, 1.0f, 0, 0, 0);

    // scores[b] = Q[b] @ K[b]^T / sqrt(H)   (batched over z)
    dim3 gs(SEQ / 128, SEQ / 128, NB);
    gemm_nt_kernel<<<gs, blk>>>(Q, K, nullptr, Sc, SEQ, SEQ, HID, 0.03125f,
                                (size_t)SEQ * HID, (size_t)SEQ * HID,
                                (size_t)SEQ * SEQ);

    // row softmax
    softmax_kernel<<<NB * SEQ, blk>>>(Sc);

    // out[b] = P[b] @ V[b]
    dim3 ga(HID / 128, SEQ / 128, NB);
    gemm_nn_kernel<<<ga, blk>>>(Sc, V, out, SEQ, HID, SEQ,
                                (size_t)SEQ * SEQ, (size_t)SEQ * HID,
                                (size_t)SEQ * HID);
}

// round 4
// speedup vs baseline: 2.2580x; 2.2580x over previous
#include <cuda_runtime.h>
#include <cuda_bf16.h>
#include <cstdint>

// Problem constants
static constexpr int HID  = 1024;
static constexpr int NB   = 4;
static constexpr int SEQ  = 2048;
static constexpr int ROWS = NB * SEQ; // 8192

// ---------------------------------------------------------------------------
// Scratch (device globals; allocation-free rule)
// ---------------------------------------------------------------------------
__device__ __nv_bfloat16 g_Xh[(size_t)ROWS * HID];
__device__ __nv_bfloat16 g_Xl[(size_t)ROWS * HID];
__device__ __nv_bfloat16 g_Wh[(size_t)3 * HID * HID];
__device__ __nv_bfloat16 g_Wl[(size_t)3 * HID * HID];
__device__ __nv_bfloat16 g_Qh[(size_t)ROWS * HID];
__device__ __nv_bfloat16 g_Ql[(size_t)ROWS * HID];
__device__ __nv_bfloat16 g_Kh[(size_t)ROWS * HID];
__device__ __nv_bfloat16 g_Kl[(size_t)ROWS * HID];
__device__ float         g_V [(size_t)ROWS * HID];
__device__ __nv_bfloat16 g_Vth[(size_t)ROWS * HID]; // [b][h][s]
__device__ __nv_bfloat16 g_Vtl[(size_t)ROWS * HID];
__device__ float         g_Sc[(size_t)NB * SEQ * SEQ];
__device__ __nv_bfloat16 g_Ph[(size_t)NB * SEQ * SEQ];
__device__ __nv_bfloat16 g_Pl[(size_t)NB * SEQ * SEQ];

// ---------------------------------------------------------------------------
// PTX helpers (sm_80-era: cp.async / ldmatrix / mma.sync — compile on sm_103)
// ---------------------------------------------------------------------------
__device__ __forceinline__ uint32_t smem_u32(const void* p) {
    uint32_t a;
    asm("{ .reg .u64 t; cvta.to.shared.u64 t, %1; cvt.u32.u64 %0, t; }"
        : "=r"(a) : "l"(p));
    return a;
}
__device__ __forceinline__ void cp_async16(uint32_t dst, const void* src) {
    asm volatile("cp.async.cg.shared.global [%0], [%1], 16;"
                 :: "r"(dst), "l"(src) : "memory");
}
#define CP_COMMIT()  asm volatile("cp.async.commit_group;" ::: "memory")
#define CP_WAIT(n)   asm volatile("cp.async.wait_group %0;" :: "n"(n) : "memory")

__device__ __forceinline__ void ldm_x4(uint32_t& r0, uint32_t& r1,
                                       uint32_t& r2, uint32_t& r3, uint32_t addr) {
    asm volatile("ldmatrix.sync.aligned.m8n8.x4.shared.b16 {%0,%1,%2,%3}, [%4];"
                 : "=r"(r0), "=r"(r1), "=r"(r2), "=r"(r3) : "r"(addr));
}
__device__ __forceinline__ void mma_bf16(float& d0, float& d1, float& d2, float& d3,
                                         uint32_t a0, uint32_t a1, uint32_t a2, uint32_t a3,
                                         uint32_t b0, uint32_t b1) {
    asm volatile(
        "mma.sync.aligned.m16n8k16.row.col.f32.bf16.bf16.f32 "
        "{%0,%1,%2,%3}, {%4,%5,%6,%7}, {%8,%9}, {%0,%1,%2,%3};"
        : "+f"(d0), "+f"(d1), "+f"(d2), "+f"(d3)
        : "r"(a0), "r"(a1), "r"(a2), "r"(a3), "r"(b0), "r"(b1));
}

// ---------------------------------------------------------------------------
// SMEM tile layout: 128 rows x 32 bf16 (64B data) stored with 80B row stride
// (16B pad). 80*r mod 128 distinct for any 8 consecutive rows -> conflict-free
// ldmatrix. 4 matrices per stage (Ah, Al, Bh, Bl), 2 stages.
// ---------------------------------------------------------------------------
static constexpr int RS        = 80;                 // bytes per row
static constexpr int MAT_BYTES = 128 * RS;           // 10240
static constexpr int STG_BYTES = 4 * MAT_BYTES;      // 40960
static constexpr int SMEM_BYTES = 2 * STG_BYTES;     // 81920

__device__ __forceinline__ void stage_load(
    const __nv_bfloat16* __restrict__ Ah, const __nv_bfloat16* __restrict__ Al,
    const __nv_bfloat16* __restrict__ Bh, const __nv_bfloat16* __restrict__ Bl,
    int K, int k0, uint32_t sb, int tid)
{
#pragma unroll
    for (int i = 0; i < 2; i++) {
        const int chunk = tid + (i << 8);
        const int row = chunk >> 2;
        const int cc  = chunk & 3;
        const size_t go = (size_t)row * K + k0 + (cc << 3);
        const uint32_t so = (uint32_t)(row * RS + (cc << 4));
        cp_async16(sb + so,                 Ah + go);
        cp_async16(sb + so + MAT_BYTES,     Al + go);
        cp_async16(sb + so + 2 * MAT_BYTES, Bh + go);
        cp_async16(sb + so + 3 * MAT_BYTES, Bl + go);
    }
}

// ---------------------------------------------------------------------------
// Generic 3-pass-bf16 GEMM NT: C = alpha*(Ahi+Alo)(Bhi+Blo)^T + bias
// A: [M,K] K-major hi/lo bf16; B: [N,K] K-major hi/lo bf16.
// C!=null -> fp32 out; Ch/Cl!=null -> split bf16 out. blockIdx.z batches.
// ---------------------------------------------------------------------------
__global__ void __launch_bounds__(256, 1)
gemm3_mma_kernel(const __nv_bfloat16* __restrict__ Ah, const __nv_bfloat16* __restrict__ Al,
                 const __nv_bfloat16* __restrict__ Bh, const __nv_bfloat16* __restrict__ Bl,
                 const float* __restrict__ bias,
                 float* __restrict__ C, __nv_bfloat16* __restrict__ Ch,
                 __nv_bfloat16* __restrict__ Cl,
                 int N, int K, float alpha,
                 size_t sA, size_t sB, size_t sC)
{
    extern __shared__ char smem[];
    const uint32_t sbase = smem_u32(smem);
    const int tid = threadIdx.x;
    const int wid = tid >> 5;
    const int lid = tid & 31;
    const int wm  = wid >> 2;   // 0..1 : 64-row slab
    const int wn  = wid & 3;    // 0..3 : 32-col slab

    const size_t offA = (size_t)blockIdx.z * sA + (size_t)blockIdx.y * 128 * K;
    const size_t offB = (size_t)blockIdx.z * sB + (size_t)blockIdx.x * 128 * K;
    const size_t zC   = (size_t)blockIdx.z * sC;
    Ah += offA; Al += offA; Bh += offB; Bl += offB;

    float acc[4][4][4];
#pragma unroll
    for (int mi = 0; mi < 4; mi++)
#pragma unroll
        for (int ni = 0; ni < 4; ni++)
#pragma unroll
            for (int r = 0; r < 4; r++) acc[mi][ni][r] = 0.0f;

    const int nch = K >> 5; // chunks of BK=32

    // Prefetch stages 0 and 1
    stage_load(Ah, Al, Bh, Bl, K, 0, sbase, tid);
    CP_COMMIT();
    stage_load(Ah, Al, Bh, Bl, K, 32, sbase + STG_BYTES, tid);
    CP_COMMIT();
    CP_WAIT(1);
    __syncthreads();

    // ldmatrix lane address components (within a 128x32 tile)
    const int a_row = wm * 64 + (((lid >> 3) & 1) << 3) + (lid & 7); // + mi*16
    const int a_chs = (lid >> 4) & 1;                                // + ks*2
    const int b_row = wn * 32 + (((lid >> 4) & 1) << 3) + (lid & 7); // + p*16
    const int b_chs = (lid >> 3) & 1;                                // + ks*2

    for (int c = 0; c < nch; c++) {
        const uint32_t tb = sbase + (uint32_t)((c & 1) * STG_BYTES);
#pragma unroll
        for (int ks = 0; ks < 2; ks++) {
            uint32_t ah[4][4], al[4][4], bh[2][4], bl[2][4];
            const uint32_t acol = (uint32_t)(((ks << 1) + a_chs) << 4);
            const uint32_t bcol = (uint32_t)(((ks << 1) + b_chs) << 4);
#pragma unroll
            for (int mi = 0; mi < 4; mi++) {
                const uint32_t ad = tb + (uint32_t)((a_row + mi * 16) * RS) + acol;
                ldm_x4(ah[mi][0], ah[mi][1], ah[mi][2], ah[mi][3], ad);
                ldm_x4(al[mi][0], al[mi][1], al[mi][2], al[mi][3], ad + MAT_BYTES);
            }
#pragma unroll
            for (int p = 0; p < 2; p++) {
                const uint32_t bd = tb + 2 * MAT_BYTES +
                                    (uint32_t)((b_row + p * 16) * RS) + bcol;
                ldm_x4(bh[p][0], bh[p][1], bh[p][2], bh[p][3], bd);
                ldm_x4(bl[p][0], bl[p][1], bl[p][2], bl[p][3], bd + MAT_BYTES);
            }
#pragma unroll
            for (int mi = 0; mi < 4; mi++)
#pragma unroll
                for (int ni = 0; ni < 4; ni++) {
                    const int pr = ni >> 1, of = (ni & 1) << 1;
                    float* d = acc[mi][ni];
                    // hi*hi
                    mma_bf16(d[0], d[1], d[2], d[3],
                             ah[mi][0], ah[mi][1], ah[mi][2], ah[mi][3],
                             bh[pr][of], bh[pr][of + 1]);
                    // hi*lo
                    mma_bf16(d[0], d[1], d[2], d[3],
                             ah[mi][0], ah[mi][1], ah[mi][2], ah[mi][3],
                             bl[pr][of], bl[pr][of + 1]);
                    // lo*hi
                    mma_bf16(d[0], d[1], d[2], d[3],
                             al[mi][0], al[mi][1], al[mi][2], al[mi][3],
                             bh[pr][of], bh[pr][of + 1]);
                }
        }
        __syncthreads();           // all warps done reading this buffer
        if (c + 2 < nch) {
            stage_load(Ah, Al, Bh, Bl, K, (c + 2) << 5,
                       sbase + (uint32_t)((c & 1) * STG_BYTES), tid);
            CP_COMMIT();
            CP_WAIT(1);            // next buffer (c+1) ready
        } else {
            CP_WAIT(0);
        }
        __syncthreads();
    }

    // Epilogue: direct register -> global stores
    const int t4 = lid >> 2;         // 0..7  row within 8
    const int t2 = (lid & 3) << 1;   // col pair
#pragma unroll
    for (int ni = 0; ni < 4; ni++) {
        const int gcol = blockIdx.x * 128 + wn * 32 + ni * 8 + t2;
        float bi0 = 0.0f, bi1 = 0.0f;
        if (bias) { bi0 = bias[gcol]; bi1 = bias[gcol + 1]; }
#pragma unroll
        for (int mi = 0; mi < 4; mi++) {
            const int grow = blockIdx.y * 128 + wm * 64 + mi * 16 + t4;
            const float* d = acc[mi][ni];
            float v00 = fmaf(alpha, d[0], bi0);
            float v01 = fmaf(alpha, d[1], bi1);
            float v10 = fmaf(alpha, d[2], bi0);
            float v11 = fmaf(alpha, d[3], bi1);
            const size_t o0 = zC + (size_t)grow * N + gcol;
            const size_t o1 = o0 + (size_t)8 * N;
            if (C) {
                *reinterpret_cast<float2*>(C + o0) = make_float2(v00, v01);
                *reinterpret_cast<float2*>(C + o1) = make_float2(v10, v11);
            }
            if (Ch) {
                __nv_bfloat16 h00 = __float2bfloat16(v00);
                __nv_bfloat16 h01 = __float2bfloat16(v01);
                __nv_bfloat16 h10 = __float2bfloat16(v10);
                __nv_bfloat16 h11 = __float2bfloat16(v11);
                *reinterpret_cast<__nv_bfloat162*>(Ch + o0) = __halves2bfloat162(h00, h01);
                *reinterpret_cast<__nv_bfloat162*>(Ch + o1) = __halves2bfloat162(h10, h11);
                __nv_bfloat16 l00 = __float2bfloat16(v00 - __bfloat162float(h00));
                __nv_bfloat16 l01 = __float2bfloat16(v01 - __bfloat162float(h01));
                __nv_bfloat16 l10 = __float2bfloat16(v10 - __bfloat162float(h10));
                __nv_bfloat16 l11 = __float2bfloat16(v11 - __bfloat162float(h11));
                *reinterpret_cast<__nv_bfloat162*>(Cl + o0) = __halves2bfloat162(l00, l01);
                *reinterpret_cast<__nv_bfloat162*>(Cl + o1) = __halves2bfloat162(l10, l11);
            }
        }
    }
}

// ---------------------------------------------------------------------------
// fp32 -> (hi, lo) bf16 split, vectorized by 4
// ---------------------------------------------------------------------------
__global__ void __launch_bounds__(256)
split_kernel(const float* __restrict__ x, __nv_bfloat16* __restrict__ hi,
             __nv_bfloat16* __restrict__ lo, int n4)
{
    int i = blockIdx.x * 256 + threadIdx.x;
    if (i >= n4) return;
    float4 v = reinterpret_cast<const float4*>(x)[i];
    __nv_bfloat16 h0 = __float2bfloat16(v.x), h1 = __float2bfloat16(v.y);
    __nv_bfloat16 h2 = __float2bfloat16(v.z), h3 = __float2bfloat16(v.w);
    __nv_bfloat16 l0 = __float2bfloat16(v.x - __bfloat162float(h0));
    __nv_bfloat16 l1 = __float2bfloat16(v.y - __bfloat162float(h1));
    __nv_bfloat16 l2 = __float2bfloat16(v.z - __bfloat162float(h2));
    __nv_bfloat16 l3 = __float2bfloat16(v.w - __bfloat162float(h3));
    reinterpret_cast<__nv_bfloat162*>(hi)[2 * i]     = __halves2bfloat162(h0, h1);
    reinterpret_cast<__nv_bfloat162*>(hi)[2 * i + 1] = __halves2bfloat162(h2, h3);
    reinterpret_cast<__nv_bfloat162*>(lo)[2 * i]     = __halves2bfloat162(l0, l1);
    reinterpret_cast<__nv_bfloat162*>(lo)[2 * i + 1] = __halves2bfloat162(l2, l3);
}

// ---------------------------------------------------------------------------
// V [b][s][h] fp32 -> Vt hi/lo [b][h][s] bf16 (transpose + split)
// ---------------------------------------------------------------------------
__global__ void __launch_bounds__(256)
transpose_split_kernel(const float* __restrict__ V,
                       __nv_bfloat16* __restrict__ Th, __nv_bfloat16* __restrict__ Tl)
{
    __shared__ float tile[32][33];
    const int b = blockIdx.z;
    const int h0 = blockIdx.x * 32, s0 = blockIdx.y * 32;
    const int tx = threadIdx.x & 31, ty = threadIdx.x >> 5; // 32 x 8
    const float* Vb = V + (size_t)b * SEQ * HID;
#pragma unroll
    for (int j = 0; j < 32; j += 8)
        tile[ty + j][tx] = Vb[(size_t)(s0 + ty + j) * HID + h0 + tx];
    __syncthreads();
    __nv_bfloat16* Thb = Th + (size_t)b * HID * SEQ;
    __nv_bfloat16* Tlb = Tl + (size_t)b * HID * SEQ;
#pragma unroll
    for (int j = 0; j < 32; j += 8) {
        float v = tile[tx][ty + j];
        __nv_bfloat16 h = __float2bfloat16(v);
        size_t o = (size_t)(h0 + ty + j) * SEQ + s0 + tx;
        Thb[o] = h;
        Tlb[o] = __float2bfloat16(v - __bfloat162float(h));
    }
}

// ---------------------------------------------------------------------------
// Row softmax (2048 cols) fused with bf16 hi/lo split of P
// ---------------------------------------------------------------------------
__global__ void __launch_bounds__(256)
softmax_split_kernel(const float* __restrict__ Sc,
                     __nv_bfloat16* __restrict__ Ph, __nv_bfloat16* __restrict__ Pl)
{
    __shared__ float red[256];
    const float* row = Sc + (size_t)blockIdx.x * SEQ;
    const int tid = threadIdx.x;

    float4 v0 = reinterpret_cast<const float4*>(row)[tid];
    float4 v1 = reinterpret_cast<const float4*>(row)[tid + 256];

    float m = fmaxf(fmaxf(fmaxf(v0.x, v0.y), fmaxf(v0.z, v0.w)),
                    fmaxf(fmaxf(v1.x, v1.y), fmaxf(v1.z, v1.w)));
    red[tid] = m;
    __syncthreads();
#pragma unroll
    for (int s = 128; s > 0; s >>= 1) {
        if (tid < s) red[tid] = fmaxf(red[tid], red[tid + s]);
        __syncthreads();
    }
    m = red[0];
    __syncthreads();

    v0.x = __expf(v0.x - m); v0.y = __expf(v0.y - m);
    v0.z = __expf(v0.z - m); v0.w = __expf(v0.w - m);
    v1.x = __expf(v1.x - m); v1.y = __expf(v1.y - m);
    v1.z = __expf(v1.z - m); v1.w = __expf(v1.w - m);

    red[tid] = v0.x + v0.y + v0.z + v0.w + v1.x + v1.y + v1.z + v1.w;
    __syncthreads();
#pragma unroll
    for (int s = 128; s > 0; s >>= 1) {
        if (tid < s) red[tid] += red[tid + s];
        __syncthreads();
    }
    const float inv = 1.0f / red[0];

    const size_t ro = (size_t)blockIdx.x * SEQ;
    __nv_bfloat162* H = reinterpret_cast<__nv_bfloat162*>(Ph + ro);
    __nv_bfloat162* L = reinterpret_cast<__nv_bfloat162*>(Pl + ro);
    float p[8] = {v0.x * inv, v0.y * inv, v0.z * inv, v0.w * inv,
                  v1.x * inv, v1.y * inv, v1.z * inv, v1.w * inv};
    __nv_bfloat16 hh[8], ll[8];
#pragma unroll
    for (int j = 0; j < 8; j++) {
        hh[j] = __float2bfloat16(p[j]);
        ll[j] = __float2bfloat16(p[j] - __bfloat162float(hh[j]));
    }
    H[2 * tid]           = __halves2bfloat162(hh[0], hh[1]);
    H[2 * tid + 1]       = __halves2bfloat162(hh[2], hh[3]);
    H[512 + 2 * tid]     = __halves2bfloat162(hh[4], hh[5]);
    H[512 + 2 * tid + 1] = __halves2bfloat162(hh[6], hh[7]);
    L[2 * tid]           = __halves2bfloat162(ll[0], ll[1]);
    L[2 * tid + 1]       = __halves2bfloat162(ll[2], ll[3]);
    L[512 + 2 * tid]     = __halves2bfloat162(ll[4], ll[5]);
    L[512 + 2 * tid + 1] = __halves2bfloat162(ll[6], ll[7]);
}

// ---------------------------------------------------------------------------
// Launch
// ---------------------------------------------------------------------------
extern "C" void kernel_launch(void* const* d_in, const int* in_sizes, int n_in,
                              void* d_out, int out_size)
{
    const float* X  = (const float*)d_in[0];
    const float* Wq = (const float*)d_in[1];
    const float* bq = (const float*)d_in[2];
    const float* Wk = (const float*)d_in[3];
    const float* bk = (const float*)d_in[4];
    const float* Wv = (const float*)d_in[5];
    const float* bv = (const float*)d_in[6];
    float* out = (float*)d_out;

    __nv_bfloat16 *Xh, *Xl, *Wh, *Wl, *Qh, *Ql, *Kh, *Kl, *Vth, *Vtl, *Ph, *Pl;
    float *V, *Sc;
    cudaGetSymbolAddress((void**)&Xh, g_Xh);   cudaGetSymbolAddress((void**)&Xl, g_Xl);
    cudaGetSymbolAddress((void**)&Wh, g_Wh);   cudaGetSymbolAddress((void**)&Wl, g_Wl);
    cudaGetSymbolAddress((void**)&Qh, g_Qh);   cudaGetSymbolAddress((void**)&Ql, g_Ql);
    cudaGetSymbolAddress((void**)&Kh, g_Kh);   cudaGetSymbolAddress((void**)&Kl, g_Kl);
    cudaGetSymbolAddress((void**)&V,  g_V);
    cudaGetSymbolAddress((void**)&Vth, g_Vth); cudaGetSymbolAddress((void**)&Vtl, g_Vtl);
    cudaGetSymbolAddress((void**)&Sc, g_Sc);
    cudaGetSymbolAddress((void**)&Ph, g_Ph);   cudaGetSymbolAddress((void**)&Pl, g_Pl);

    cudaFuncSetAttribute(gemm3_mma_kernel,
                         cudaFuncAttributeMaxDynamicSharedMemorySize, SMEM_BYTES);

    // Split inputs to bf16 hi/lo
    {
        int n4 = ROWS * HID / 4;
        split_kernel<<<(n4 + 255) / 256, 256>>>(X, Xh, Xl, n4);
        int w4 = HID * HID / 4;
        split_kernel<<<(w4 + 255) / 256, 256>>>(Wq, Wh, Wl, w4);
        split_kernel<<<(w4 + 255) / 256, 256>>>(Wk, Wh + (size_t)HID * HID,
                                                Wl + (size_t)HID * HID, w4);
        split_kernel<<<(w4 + 255) / 256, 256>>>(Wv, Wh + (size_t)2 * HID * HID,
                                                Wl + (size_t)2 * HID * HID, w4);
    }

    dim3 blk(256);

    // QKV projections: [8192,1024] = X @ W^T + b (Q,K split output; V fp32)
    dim3 gq(HID / 128, ROWS / 128, 1);
    gemm3_mma_kernel<<<gq, blk, SMEM_BYTES>>>(Xh, Xl, Wh, Wl, bq,
                                              nullptr, Qh, Ql,
                                              HID, HID, 1.0f, 0, 0, 0);
    gemm3_mma_kernel<<<gq, blk, SMEM_BYTES>>>(Xh, Xl,
                                              Wh + (size_t)HID * HID, Wl + (size_t)HID * HID, bk,
                                              nullptr, Kh, Kl,
                                              HID, HID, 1.0f, 0, 0, 0);
    gemm3_mma_kernel<<<gq, blk, SMEM_BYTES>>>(Xh, Xl,
                                              Wh + (size_t)2 * HID * HID, Wl + (size_t)2 * HID * HID, bv,
                                              V, nullptr, nullptr,
                                              HID, HID, 1.0f, 0, 0, 0);

    // V -> Vt hi/lo (per batch: [h][s])
    {
        dim3 gt(HID / 32, SEQ / 32, NB);
        transpose_split_kernel<<<gt, 256>>>(V, Vth, Vtl);
    }

    // scores[b] = Q[b] @ K[b]^T / 32
    dim3 gs(SEQ / 128, SEQ / 128, NB);
    gemm3_mma_kernel<<<gs, blk, SMEM_BYTES>>>(Qh, Ql, Kh, Kl, nullptr,
                                              Sc, nullptr, nullptr,
                                              SEQ, HID, 0.03125f,
                                              (size_t)SEQ * HID, (size_t)SEQ * HID,
                                              (size_t)SEQ * SEQ);

    // softmax + split P
    softmax_split_kernel<<<NB * SEQ, 256>>>(Sc, Ph, Pl);

    // out[b] = P[b] @ Vt[b]^T  (Vt is [N=hid, K=seq] K-major)
    dim3 ga(HID / 128, SEQ / 128, NB);
    gemm3_mma_kernel<<<ga, blk, SMEM_BYTES>>>(Ph, Pl, Vth, Vtl, nullptr,
                                              out, nullptr, nullptr,
                                              HID, SEQ, 1.0f,
                                              (size_t)SEQ * SEQ, (size_t)SEQ * HID,
                                              (size_t)SEQ * HID);
}

// round 5
// speedup vs baseline: 2.6261x; 1.1631x over previous
#include <cuda_runtime.h>
#include <cuda_bf16.h>
#include <cstdint>

// Problem constants
static constexpr int HID  = 1024;
static constexpr int NB   = 4;
static constexpr int SEQ  = 2048;
static constexpr int ROWS = NB * SEQ; // 8192

// ---------------------------------------------------------------------------
// Scratch (device globals; allocation-free rule)
// ---------------------------------------------------------------------------
__device__ __nv_bfloat16 g_Xh[(size_t)ROWS * HID];
__device__ __nv_bfloat16 g_Xl[(size_t)ROWS * HID];
__device__ __nv_bfloat16 g_Wh[(size_t)3 * HID * HID];
__device__ __nv_bfloat16 g_Wl[(size_t)3 * HID * HID];
__device__ __nv_bfloat16 g_Qh[(size_t)ROWS * HID];
__device__ __nv_bfloat16 g_Ql[(size_t)ROWS * HID];
__device__ __nv_bfloat16 g_Kh[(size_t)ROWS * HID];
__device__ __nv_bfloat16 g_Kl[(size_t)ROWS * HID];
__device__ float         g_V [(size_t)ROWS * HID];
__device__ __nv_bfloat16 g_Vth[(size_t)ROWS * HID]; // [b][h][s]
__device__ __nv_bfloat16 g_Vtl[(size_t)ROWS * HID];
__device__ float         g_Sc[(size_t)NB * SEQ * SEQ];
__device__ __nv_bfloat16 g_Ph[(size_t)NB * SEQ * SEQ];
__device__ __nv_bfloat16 g_Pl[(size_t)NB * SEQ * SEQ];

// ---------------------------------------------------------------------------
// PTX helpers (sm_80-era: cp.async / ldmatrix / mma.sync — compile on sm_103)
// ---------------------------------------------------------------------------
__device__ __forceinline__ uint32_t smem_u32(const void* p) {
    uint32_t a;
    asm("{ .reg .u64 t; cvta.to.shared.u64 t, %1; cvt.u32.u64 %0, t; }"
        : "=r"(a) : "l"(p));
    return a;
}
__device__ __forceinline__ void cp_async16(uint32_t dst, const void* src) {
    asm volatile("cp.async.cg.shared.global [%0], [%1], 16;"
                 :: "r"(dst), "l"(src) : "memory");
}
#define CP_COMMIT()  asm volatile("cp.async.commit_group;" ::: "memory")
#define CP_WAIT(n)   asm volatile("cp.async.wait_group %0;" :: "n"(n) : "memory")

__device__ __forceinline__ void ldm_x4(uint32_t& r0, uint32_t& r1,
                                       uint32_t& r2, uint32_t& r3, uint32_t addr) {
    asm volatile("ldmatrix.sync.aligned.m8n8.x4.shared.b16 {%0,%1,%2,%3}, [%4];"
                 : "=r"(r0), "=r"(r1), "=r"(r2), "=r"(r3) : "r"(addr));
}
__device__ __forceinline__ void mma_bf16(float& d0, float& d1, float& d2, float& d3,
                                         uint32_t a0, uint32_t a1, uint32_t a2, uint32_t a3,
                                         uint32_t b0, uint32_t b1) {
    asm volatile(
        "mma.sync.aligned.m16n8k16.row.col.f32.bf16.bf16.f32 "
        "{%0,%1,%2,%3}, {%4,%5,%6,%7}, {%8,%9}, {%0,%1,%2,%3};"
        : "+f"(d0), "+f"(d1), "+f"(d2), "+f"(d3)
        : "r"(a0), "r"(a1), "r"(a2), "r"(a3), "r"(b0), "r"(b1));
}

// ---------------------------------------------------------------------------
// SMEM tile layout: 128 rows x 32 bf16 (64B data) stored with 80B row stride
// (16B pad). 80*r mod 128 distinct for any 8 consecutive rows -> conflict-free
// ldmatrix. 4 matrices per stage (Ah, Al, Bh, Bl), 2 stages.
// ---------------------------------------------------------------------------
static constexpr int RS        = 80;                 // bytes per row
static constexpr int MAT_BYTES = 128 * RS;           // 10240
static constexpr int STG_BYTES = 4 * MAT_BYTES;      // 40960
static constexpr int SMEM_BYTES = 2 * STG_BYTES;     // 81920 (x2 CTAs = 160K <= 228K)

__device__ __forceinline__ void stage_load(
    const __nv_bfloat16* __restrict__ Ah, const __nv_bfloat16* __restrict__ Al,
    const __nv_bfloat16* __restrict__ Bh, const __nv_bfloat16* __restrict__ Bl,
    int K, int k0, uint32_t sb, int tid)
{
#pragma unroll
    for (int i = 0; i < 2; i++) {
        const int chunk = tid + (i << 8);
        const int row = chunk >> 2;
        const int cc  = chunk & 3;
        const size_t go = (size_t)row * K + k0 + (cc << 3);
        const uint32_t so = (uint32_t)(row * RS + (cc << 4));
        cp_async16(sb + so,                 Ah + go);
        cp_async16(sb + so + MAT_BYTES,     Al + go);
        cp_async16(sb + so + 2 * MAT_BYTES, Bh + go);
        cp_async16(sb + so + 3 * MAT_BYTES, Bl + go);
    }
}

// ---------------------------------------------------------------------------
// Generic 3-pass-bf16 GEMM NT: C = alpha*(Ahi+Alo)(Bhi+Blo)^T + bias
// A: [M,K] K-major hi/lo bf16; B: [N,K] K-major hi/lo bf16.
// C!=null -> fp32 out; Ch/Cl!=null -> split bf16 out. blockIdx.z batches.
// 2 CTAs/SM for stall hiding.
// ---------------------------------------------------------------------------
__global__ void __launch_bounds__(256, 2)
gemm3_mma_kernel(const __nv_bfloat16* __restrict__ Ah, const __nv_bfloat16* __restrict__ Al,
                 const __nv_bfloat16* __restrict__ Bh, const __nv_bfloat16* __restrict__ Bl,
                 const float* __restrict__ bias,
                 float* __restrict__ C, __nv_bfloat16* __restrict__ Ch,
                 __nv_bfloat16* __restrict__ Cl,
                 int N, int K, float alpha,
                 size_t sA, size_t sB, size_t sC)
{
    extern __shared__ char smem[];
    const uint32_t sbase = smem_u32(smem);
    const int tid = threadIdx.x;
    const int wid = tid >> 5;
    const int lid = tid & 31;
    const int wm  = wid >> 2;   // 0..1 : 64-row slab
    const int wn  = wid & 3;    // 0..3 : 32-col slab

    const size_t offA = (size_t)blockIdx.z * sA + (size_t)blockIdx.y * 128 * K;
    const size_t offB = (size_t)blockIdx.z * sB + (size_t)blockIdx.x * 128 * K;
    const size_t zC   = (size_t)blockIdx.z * sC;
    Ah += offA; Al += offA; Bh += offB; Bl += offB;

    float acc[4][4][4];
#pragma unroll
    for (int mi = 0; mi < 4; mi++)
#pragma unroll
        for (int ni = 0; ni < 4; ni++)
#pragma unroll
            for (int r = 0; r < 4; r++) acc[mi][ni][r] = 0.0f;

    const int nch = K >> 5; // chunks of BK=32

    // Prefetch stages 0 and 1
    stage_load(Ah, Al, Bh, Bl, K, 0, sbase, tid);
    CP_COMMIT();
    stage_load(Ah, Al, Bh, Bl, K, 32, sbase + STG_BYTES, tid);
    CP_COMMIT();
    CP_WAIT(1);
    __syncthreads();

    // ldmatrix lane address components (within a 128x32 tile)
    const int a_row = wm * 64 + (((lid >> 3) & 1) << 3) + (lid & 7); // + mi*16
    const int a_chs = (lid >> 4) & 1;                                // + ks*2
    const int b_row = wn * 32 + (((lid >> 4) & 1) << 3) + (lid & 7); // + p*16
    const int b_chs = (lid >> 3) & 1;                                // + ks*2

    for (int c = 0; c < nch; c++) {
        const uint32_t tb = sbase + (uint32_t)((c & 1) * STG_BYTES);
#pragma unroll
        for (int ks = 0; ks < 2; ks++) {
            uint32_t ah[4][4], al[4][4];
            const uint32_t acol = (uint32_t)(((ks << 1) + a_chs) << 4);
            const uint32_t bcol = (uint32_t)(((ks << 1) + b_chs) << 4);
#pragma unroll
            for (int mi = 0; mi < 4; mi++) {
                const uint32_t ad = tb + (uint32_t)((a_row + mi * 16) * RS) + acol;
                ldm_x4(ah[mi][0], ah[mi][1], ah[mi][2], ah[mi][3], ad);
                ldm_x4(al[mi][0], al[mi][1], al[mi][2], al[mi][3], ad + MAT_BYTES);
            }
            // B fragments loaded per 16-col slab to cap live registers (~8 B regs)
#pragma unroll
            for (int pr = 0; pr < 2; pr++) {
                uint32_t bh[4], bl[4];
                const uint32_t bd = tb + 2 * MAT_BYTES +
                                    (uint32_t)((b_row + pr * 16) * RS) + bcol;
                ldm_x4(bh[0], bh[1], bh[2], bh[3], bd);
                ldm_x4(bl[0], bl[1], bl[2], bl[3], bd + MAT_BYTES);
#pragma unroll
                for (int mi = 0; mi < 4; mi++)
#pragma unroll
                    for (int q = 0; q < 2; q++) {
                        const int of = q << 1;
                        float* d = acc[mi][pr * 2 + q];
                        // hi*hi
                        mma_bf16(d[0], d[1], d[2], d[3],
                                 ah[mi][0], ah[mi][1], ah[mi][2], ah[mi][3],
                                 bh[of], bh[of + 1]);
                        // hi*lo
                        mma_bf16(d[0], d[1], d[2], d[3],
                                 ah[mi][0], ah[mi][1], ah[mi][2], ah[mi][3],
                                 bl[of], bl[of + 1]);
                        // lo*hi
                        mma_bf16(d[0], d[1], d[2], d[3],
                                 al[mi][0], al[mi][1], al[mi][2], al[mi][3],
                                 bh[of], bh[of + 1]);
                    }
            }
        }
        __syncthreads();           // all warps done reading this buffer
        if (c + 2 < nch) {
            stage_load(Ah, Al, Bh, Bl, K, (c + 2) << 5,
                       sbase + (uint32_t)((c & 1) * STG_BYTES), tid);
            CP_COMMIT();
            CP_WAIT(1);            // next buffer (c+1) ready
        } else {
            CP_WAIT(0);
        }
        __syncthreads();
    }

    // Epilogue: direct register -> global stores
    const int t4 = lid >> 2;         // 0..7  row within 8
    const int t2 = (lid & 3) << 1;   // col pair
#pragma unroll
    for (int ni = 0; ni < 4; ni++) {
        const int gcol = blockIdx.x * 128 + wn * 32 + ni * 8 + t2;
        float bi0 = 0.0f, bi1 = 0.0f;
        if (bias) { bi0 = bias[gcol]; bi1 = bias[gcol + 1]; }
#pragma unroll
        for (int mi = 0; mi < 4; mi++) {
            const int grow = blockIdx.y * 128 + wm * 64 + mi * 16 + t4;
            const float* d = acc[mi][ni];
            float v00 = fmaf(alpha, d[0], bi0);
            float v01 = fmaf(alpha, d[1], bi1);
            float v10 = fmaf(alpha, d[2], bi0);
            float v11 = fmaf(alpha, d[3], bi1);
            const size_t o0 = zC + (size_t)grow * N + gcol;
            const size_t o1 = o0 + (size_t)8 * N;
            if (C) {
                *reinterpret_cast<float2*>(C + o0) = make_float2(v00, v01);
                *reinterpret_cast<float2*>(C + o1) = make_float2(v10, v11);
            }
            if (Ch) {
                __nv_bfloat16 h00 = __float2bfloat16(v00);
                __nv_bfloat16 h01 = __float2bfloat16(v01);
                __nv_bfloat16 h10 = __float2bfloat16(v10);
                __nv_bfloat16 h11 = __float2bfloat16(v11);
                *reinterpret_cast<__nv_bfloat162*>(Ch + o0) = __halves2bfloat162(h00, h01);
                *reinterpret_cast<__nv_bfloat162*>(Ch + o1) = __halves2bfloat162(h10, h11);
                __nv_bfloat16 l00 = __float2bfloat16(v00 - __bfloat162float(h00));
                __nv_bfloat16 l01 = __float2bfloat16(v01 - __bfloat162float(h01));
                __nv_bfloat16 l10 = __float2bfloat16(v10 - __bfloat162float(h10));
                __nv_bfloat16 l11 = __float2bfloat16(v11 - __bfloat162float(h11));
                *reinterpret_cast<__nv_bfloat162*>(Cl + o0) = __halves2bfloat162(l00, l01);
                *reinterpret_cast<__nv_bfloat162*>(Cl + o1) = __halves2bfloat162(l10, l11);
            }
        }
    }
}

// ---------------------------------------------------------------------------
// fp32 -> (hi, lo) bf16 split, vectorized by 4
// ---------------------------------------------------------------------------
__global__ void __launch_bounds__(256)
split_kernel(const float* __restrict__ x, __nv_bfloat16* __restrict__ hi,
             __nv_bfloat16* __restrict__ lo, int n4)
{
    int i = blockIdx.x * 256 + threadIdx.x;
    if (i >= n4) return;
    float4 v = reinterpret_cast<const float4*>(x)[i];
    __nv_bfloat16 h0 = __float2bfloat16(v.x), h1 = __float2bfloat16(v.y);
    __nv_bfloat16 h2 = __float2bfloat16(v.z), h3 = __float2bfloat16(v.w);
    __nv_bfloat16 l0 = __float2bfloat16(v.x - __bfloat162float(h0));
    __nv_bfloat16 l1 = __float2bfloat16(v.y - __bfloat162float(h1));
    __nv_bfloat16 l2 = __float2bfloat16(v.z - __bfloat162float(h2));
    __nv_bfloat16 l3 = __float2bfloat16(v.w - __bfloat162float(h3));
    reinterpret_cast<__nv_bfloat162*>(hi)[2 * i]     = __halves2bfloat162(h0, h1);
    reinterpret_cast<__nv_bfloat162*>(hi)[2 * i + 1] = __halves2bfloat162(h2, h3);
    reinterpret_cast<__nv_bfloat162*>(lo)[2 * i]     = __halves2bfloat162(l0, l1);
    reinterpret_cast<__nv_bfloat162*>(lo)[2 * i + 1] = __halves2bfloat162(l2, l3);
}

// ---------------------------------------------------------------------------
// V [b][s][h] fp32 -> Vt hi/lo [b][h][s] bf16 (transpose + split)
// ---------------------------------------------------------------------------
__global__ void __launch_bounds__(256)
transpose_split_kernel(const float* __restrict__ V,
                       __nv_bfloat16* __restrict__ Th, __nv_bfloat16* __restrict__ Tl)
{
    __shared__ float tile[32][33];
    const int b = blockIdx.z;
    const int h0 = blockIdx.x * 32, s0 = blockIdx.y * 32;
    const int tx = threadIdx.x & 31, ty = threadIdx.x >> 5; // 32 x 8
    const float* Vb = V + (size_t)b * SEQ * HID;
#pragma unroll
    for (int j = 0; j < 32; j += 8)
        tile[ty + j][tx] = Vb[(size_t)(s0 + ty + j) * HID + h0 + tx];
    __syncthreads();
    __nv_bfloat16* Thb = Th + (size_t)b * HID * SEQ;
    __nv_bfloat16* Tlb = Tl + (size_t)b * HID * SEQ;
#pragma unroll
    for (int j = 0; j < 32; j += 8) {
        float v = tile[tx][ty + j];
        __nv_bfloat16 h = __float2bfloat16(v);
        size_t o = (size_t)(h0 + ty + j) * SEQ + s0 + tx;
        Thb[o] = h;
        Tlb[o] = __float2bfloat16(v - __bfloat162float(h));
    }
}

// ---------------------------------------------------------------------------
// Row softmax (2048 cols) fused with bf16 hi/lo split of P
// ---------------------------------------------------------------------------
__global__ void __launch_bounds__(256)
softmax_split_kernel(const float* __restrict__ Sc,
                     __nv_bfloat16* __restrict__ Ph, __nv_bfloat16* __restrict__ Pl)
{
    __shared__ float red[256];
    const float* row = Sc + (size_t)blockIdx.x * SEQ;
    const int tid = threadIdx.x;

    float4 v0 = reinterpret_cast<const float4*>(row)[tid];
    float4 v1 = reinterpret_cast<const float4*>(row)[tid + 256];

    float m = fmaxf(fmaxf(fmaxf(v0.x, v0.y), fmaxf(v0.z, v0.w)),
                    fmaxf(fmaxf(v1.x, v1.y), fmaxf(v1.z, v1.w)));
    red[tid] = m;
    __syncthreads();
#pragma unroll
    for (int s = 128; s > 0; s >>= 1) {
        if (tid < s) red[tid] = fmaxf(red[tid], red[tid + s]);
        __syncthreads();
    }
    m = red[0];
    __syncthreads();

    v0.x = __expf(v0.x - m); v0.y = __expf(v0.y - m);
    v0.z = __expf(v0.z - m); v0.w = __expf(v0.w - m);
    v1.x = __expf(v1.x - m); v1.y = __expf(v1.y - m);
    v1.z = __expf(v1.z - m); v1.w = __expf(v1.w - m);

    red[tid] = v0.x + v0.y + v0.z + v0.w + v1.x + v1.y + v1.z + v1.w;
    __syncthreads();
#pragma unroll
    for (int s = 128; s > 0; s >>= 1) {
        if (tid < s) red[tid] += red[tid + s];
        __syncthreads();
    }
    const float inv = 1.0f / red[0];

    const size_t ro = (size_t)blockIdx.x * SEQ;
    __nv_bfloat162* H = reinterpret_cast<__nv_bfloat162*>(Ph + ro);
    __nv_bfloat162* L = reinterpret_cast<__nv_bfloat162*>(Pl + ro);
    float p[8] = {v0.x * inv, v0.y * inv, v0.z * inv, v0.w * inv,
                  v1.x * inv, v1.y * inv, v1.z * inv, v1.w * inv};
    __nv_bfloat16 hh[8], ll[8];
#pragma unroll
    for (int j = 0; j < 8; j++) {
        hh[j] = __float2bfloat16(p[j]);
        ll[j] = __float2bfloat16(p[j] - __bfloat162float(hh[j]));
    }
    H[2 * tid]           = __halves2bfloat162(hh[0], hh[1]);
    H[2 * tid + 1]       = __halves2bfloat162(hh[2], hh[3]);
    H[512 + 2 * tid]     = __halves2bfloat162(hh[4], hh[5]);
    H[512 + 2 * tid + 1] = __halves2bfloat162(hh[6], hh[7]);
    L[2 * tid]           = __halves2bfloat162(ll[0], ll[1]);
    L[2 * tid + 1]       = __halves2bfloat162(ll[2], ll[3]);
    L[512 + 2 * tid]     = __halves2bfloat162(ll[4], ll[5]);
    L[512 + 2 * tid + 1] = __halves2bfloat162(ll[6], ll[7]);
}

// ---------------------------------------------------------------------------
// Launch
// ---------------------------------------------------------------------------
extern "C" void kernel_launch(void* const* d_in, const int* in_sizes, int n_in,
                              void* d_out, int out_size)
{
    const float* X  = (const float*)d_in[0];
    const float* Wq = (const float*)d_in[1];
    const float* bq = (const float*)d_in[2];
    const float* Wk = (const float*)d_in[3];
    const float* bk = (const float*)d_in[4];
    const float* Wv = (const float*)d_in[5];
    const float* bv = (const float*)d_in[6];
    float* out = (float*)d_out;

    __nv_bfloat16 *Xh, *Xl, *Wh, *Wl, *Qh, *Ql, *Kh, *Kl, *Vth, *Vtl, *Ph, *Pl;
    float *V, *Sc;
    cudaGetSymbolAddress((void**)&Xh, g_Xh);   cudaGetSymbolAddress((void**)&Xl, g_Xl);
    cudaGetSymbolAddress((void**)&Wh, g_Wh);   cudaGetSymbolAddress((void**)&Wl, g_Wl);
    cudaGetSymbolAddress((void**)&Qh, g_Qh);   cudaGetSymbolAddress((void**)&Ql, g_Ql);
    cudaGetSymbolAddress((void**)&Kh, g_Kh);   cudaGetSymbolAddress((void**)&Kl, g_Kl);
    cudaGetSymbolAddress((void**)&V,  g_V);
    cudaGetSymbolAddress((void**)&Vth, g_Vth); cudaGetSymbolAddress((void**)&Vtl, g_Vtl);
    cudaGetSymbolAddress((void**)&Sc, g_Sc);
    cudaGetSymbolAddress((void**)&Ph, g_Ph);   cudaGetSymbolAddress((void**)&Pl, g_Pl);

    cudaFuncSetAttribute(gemm3_mma_kernel,
                         cudaFuncAttributeMaxDynamicSharedMemorySize, SMEM_BYTES);

    // Split inputs to bf16 hi/lo
    {
        int n4 = ROWS * HID / 4;
        split_kernel<<<(n4 + 255) / 256, 256>>>(X, Xh, Xl, n4);
        int w4 = HID * HID / 4;
        split_kernel<<<(w4 + 255) / 256, 256>>>(Wq, Wh, Wl, w4);
        split_kernel<<<(w4 + 255) / 256, 256>>>(Wk, Wh + (size_t)HID * HID,
                                                Wl + (size_t)HID * HID, w4);
        split_kernel<<<(w4 + 255) / 256, 256>>>(Wv, Wh + (size_t)2 * HID * HID,
                                                Wl + (size_t)2 * HID * HID, w4);
    }

    dim3 blk(256);

    // QKV projections: [8192,1024] = X @ W^T + b (Q,K split output; V fp32)
    dim3 gq(HID / 128, ROWS / 128, 1);
    gemm3_mma_kernel<<<gq, blk, SMEM_BYTES>>>(Xh, Xl, Wh, Wl, bq,
                                              nullptr, Qh, Ql,
                                              HID, HID, 1.0f, 0, 0, 0);
    gemm3_mma_kernel<<<gq, blk, SMEM_BYTES>>>(Xh, Xl,
                                              Wh + (size_t)HID * HID, Wl + (size_t)HID * HID, bk,
                                              nullptr, Kh, Kl,
                                              HID, HID, 1.0f, 0, 0, 0);
    gemm3_mma_kernel<<<gq, blk, SMEM_BYTES>>>(Xh, Xl,
                                              Wh + (size_t)2 * HID * HID, Wl + (size_t)2 * HID * HID, bv,
                                              V, nullptr, nullptr,
                                              HID, HID, 1.0f, 0, 0, 0);

    // V -> Vt hi/lo (per batch: [h][s])
    {
        dim3 gt(HID / 32, SEQ / 32, NB);
        transpose_split_kernel<<<gt, 256>>>(V, Vth, Vtl);
    }

    // scores[b] = Q[b] @ K[b]^T / 32
    dim3 gs(SEQ / 128, SEQ / 128, NB);
    gemm3_mma_kernel<<<gs, blk, SMEM_BYTES>>>(Qh, Ql, Kh, Kl, nullptr,
                                              Sc, nullptr, nullptr,
                                              SEQ, HID, 0.03125f,
                                              (size_t)SEQ * HID, (size_t)SEQ * HID,
                                              (size_t)SEQ * SEQ);

    // softmax + split P
    softmax_split_kernel<<<NB * SEQ, 256>>>(Sc, Ph, Pl);

    // out[b] = P[b] @ Vt[b]^T  (Vt is [N=hid, K=seq] K-major)
    dim3 ga(HID / 128, SEQ / 128, NB);
    gemm3_mma_kernel<<<ga, blk, SMEM_BYTES>>>(Ph, Pl, Vth, Vtl, nullptr,
                                              out, nullptr, nullptr,
                                              HID, SEQ, 1.0f,
                                              (size_t)SEQ * SEQ, (size_t)SEQ * HID,
                                              (size_t)SEQ * HID);
}